// round 9
// baseline (speedup 1.0000x reference)
#include <cuda_runtime.h>

#define LL 4096
#define CC 16
#define NB 16
#define OC 64
#define KS 7

typedef unsigned long long u64;

__device__ __forceinline__ u64 pack2(float lo, float hi) {
    u64 r;
    asm("mov.b64 %0, {%1, %2};" : "=l"(r) : "f"(lo), "f"(hi));
    return r;
}
__device__ __forceinline__ u64 ffma2(u64 a, u64 b, u64 c) {
    u64 d;
    asm("fma.rn.f32x2 %0, %1, %2, %3;" : "=l"(d) : "l"(a), "l"(b), "l"(c));
    return d;
}
__device__ __forceinline__ u64 fmul2(u64 a, u64 b) {
    u64 d;
    asm("mul.rn.f32x2 %0, %1, %2;" : "=l"(d) : "l"(a), "l"(b));
    return d;
}
__device__ __forceinline__ void unpack2(u64 v, float& lo, float& hi) {
    asm("mov.b64 {%0, %1}, %2;" : "=f"(lo), "=f"(hi) : "l"(v));
}

__global__ __launch_bounds__(128, 9) void deform_conv_kernel(
    const float* __restrict__ x,
    const float* __restrict__ pw, const float* __restrict__ pb,
    const float* __restrict__ mw, const float* __restrict__ mb,
    const float* __restrict__ cw, const float* __restrict__ cb,
    float* __restrict__ out)
{
    // conv weights: [oc][8] scalar floats, taps 0-6 + bias in slot 7.
    // Read in epilogue as u64 pairs: (w0,w1)(w2,w3)(w4,w5)(w6,bias).
    __shared__ float s_w8[OC][8];
    // prep conv weights, lane-duplicated (tiny, read once per tap)
    __shared__ u64 s_pwd[KS * 3], s_pbd[KS], s_mwd[KS * 3], s_mbd[KS];

    const int tid = threadIdx.x;
    for (int i = tid; i < OC * 8; i += blockDim.x) {
        const int oc = i >> 3, k = i & 7;
        s_w8[oc][k] = (k < KS) ? cw[oc * KS + k] : cb[oc];
    }
    if (tid < KS * 3) {
        const float a = pw[tid], c = mw[tid];
        s_pwd[tid] = pack2(a, a);
        s_mwd[tid] = pack2(c, c);
    }
    if (tid < KS) {
        const float a = pb[tid], c = mb[tid];
        s_pbd[tid] = pack2(a, a);
        s_mbd[tid] = pack2(c, c);
    }
    __syncthreads();

    const int t  = blockIdx.x * blockDim.x + tid;   // 2^18 threads total
    const int c4 = t & 3;                           // 4-channel group
    const int l  = (t >> 2) & (LL - 1);
    const int b  = t >> 14;                         // 4*LL = 2^14 per batch

    const float* xb = x + b * (LL * CC);
    const float4* xb4 = (const float4*)xb;

    // 3-tap window over 4 channels (zero padding at the edges, pad=1 conv)
    float4 sm1 = (l > 0)      ? xb4[(l - 1) * 4 + c4] : make_float4(0.f, 0.f, 0.f, 0.f);
    float4 s0  =                xb4[l * 4 + c4];
    float4 sp1 = (l < LL - 1) ? xb4[(l + 1) * 4 + c4] : make_float4(0.f, 0.f, 0.f, 0.f);

    // channel-paired window values: pair A = ch0,1; pair B = ch2,3
    const u64 wA0 = pack2(sm1.x, sm1.y), wB0 = pack2(sm1.z, sm1.w);
    const u64 wA1 = pack2(s0.x,  s0.y),  wB1 = pack2(s0.z,  s0.w);
    const u64 wA2 = pack2(sp1.x, sp1.y), wB2 = pack2(sp1.z, sp1.w);

    float vk[4][KS];
    #pragma unroll
    for (int k = 0; k < KS; ++k) {
        const u64 pk0 = s_pwd[k * 3], pk1 = s_pwd[k * 3 + 1], pk2 = s_pwd[k * 3 + 2];
        const u64 mk0 = s_mwd[k * 3], mk1 = s_mwd[k * 3 + 1], mk2 = s_mwd[k * 3 + 2];
        u64 offA = ffma2(wA2, pk2, ffma2(wA1, pk1, ffma2(wA0, pk0, s_pbd[k])));
        u64 offB = ffma2(wB2, pk2, ffma2(wB1, pk1, ffma2(wB0, pk0, s_pbd[k])));
        u64 zA   = ffma2(wA2, mk2, ffma2(wA1, mk1, ffma2(wA0, mk0, s_mbd[k])));
        u64 zB   = ffma2(wB2, mk2, ffma2(wB1, mk1, ffma2(wB0, mk0, s_mbd[k])));
        float offc[4], zc[4];
        unpack2(offA, offc[0], offc[1]);
        unpack2(offB, offc[2], offc[3]);
        unpack2(zA,   zc[0],   zc[1]);
        unpack2(zB,   zc[2],   zc[3]);

        const float pbase = (float)(l + 1 + (k - 3));   // p_0 is 1-indexed
        #pragma unroll
        for (int i = 0; i < 4; ++i) {
            float m   = __fdividef(1.f, 1.f + __expf(-zc[i]));  // sigmoid
            float p   = pbase + offc[i];
            float qlt = fminf(fmaxf(floorf(p), 0.f), (float)(LL - 1));
            float qrb = fminf(qlt + 1.f, (float)(LL - 1));
            float pc  = fminf(fmaxf(p, 0.f), (float)(LL - 1));
            float glt = 1.f + (qlt - pc);
            float grb = 1.f - (qrb - pc);
            const int ch = c4 * 4 + i;
            float xlt = xb[(int)qlt * CC + ch];
            float xrb = xb[(int)qrb * CC + ch];
            vk[i][k] = (glt * xlt + grb * xrb) * m;
        }
    }

    // tap-paired packed v values per channel (natural pairs, no duplication)
    u64 v01[4], v23[4], v45[4], v6b[4];
    #pragma unroll
    for (int i = 0; i < 4; ++i) {
        v01[i] = pack2(vk[i][0], vk[i][1]);
        v23[i] = pack2(vk[i][2], vk[i][3]);
        v45[i] = pack2(vk[i][4], vk[i][5]);
        v6b[i] = pack2(vk[i][6], 1.f);          // lane1 multiplies the bias
    }

    float4* out4 = (float4*)out;
    const int obase = ((b * OC) * LL + l) * 4 + c4;     // float4 index

    #pragma unroll 4
    for (int oc = 0; oc < OC; ++oc) {
        const ulonglong2* row = (const ulonglong2*)s_w8[oc];
        ulonglong2 wa = row[0];     // (w0,w1) (w2,w3)
        ulonglong2 wb = row[1];     // (w4,w5) (w6,bias)
        float r[4];
        #pragma unroll
        for (int i = 0; i < 4; ++i) {
            u64 acc = fmul2(v6b[i], wb.y);              // (w6*v6, bias)
            acc = ffma2(v01[i], wa.x, acc);
            acc = ffma2(v23[i], wa.y, acc);
            acc = ffma2(v45[i], wb.x, acc);
            float lo, hi;
            unpack2(acc, lo, hi);
            r[i] = lo + hi;
        }
        __stcs(&out4[obase + oc * (LL * 4)], make_float4(r[0], r[1], r[2], r[3]));
    }
}

extern "C" void kernel_launch(void* const* d_in, const int* in_sizes, int n_in,
                              void* d_out, int out_size)
{
    const float* x  = (const float*)d_in[0];
    const float* pw = (const float*)d_in[1];
    const float* pb = (const float*)d_in[2];
    const float* mw = (const float*)d_in[3];
    const float* mb = (const float*)d_in[4];
    const float* cw = (const float*)d_in[5];
    const float* cb = (const float*)d_in[6];
    float* out = (float*)d_out;

    // 16 batches * 4096 positions * 4 channel-groups = 262144 threads
    deform_conv_kernel<<<2048, 128>>>(x, pw, pb, mw, mb, cw, cb, out);
}

// round 10
// speedup vs baseline: 1.1325x; 1.1325x over previous
#include <cuda_runtime.h>

#define LL 4096
#define CC 16
#define NB 16
#define OC 64
#define KS 7

typedef unsigned long long u64;

__device__ __forceinline__ u64 pack2(float lo, float hi) {
    u64 r;
    asm("mov.b64 %0, {%1, %2};" : "=l"(r) : "f"(lo), "f"(hi));
    return r;
}
__device__ __forceinline__ u64 ffma2(u64 a, u64 b, u64 c) {
    u64 d;
    asm("fma.rn.f32x2 %0, %1, %2, %3;" : "=l"(d) : "l"(a), "l"(b), "l"(c));
    return d;
}
__device__ __forceinline__ u64 fmul2(u64 a, u64 b) {
    u64 d;
    asm("mul.rn.f32x2 %0, %1, %2;" : "=l"(d) : "l"(a), "l"(b));
    return d;
}
__device__ __forceinline__ void unpack2(u64 v, float& lo, float& hi) {
    asm("mov.b64 {%0, %1}, %2;" : "=f"(lo), "=f"(hi) : "l"(v));
}

__global__ __launch_bounds__(256, 5) void deform_conv_kernel(
    const float* __restrict__ x,
    const float* __restrict__ pw, const float* __restrict__ pb,
    const float* __restrict__ mw, const float* __restrict__ mb,
    const float* __restrict__ cw, const float* __restrict__ cb,
    float* __restrict__ out)
{
    // conv weights: [oc][8] scalar floats, taps 0-6 + bias in slot 7.
    // Read in epilogue as u64 pairs: (w0,w1)(w2,w3)(w4,w5)(w6,bias).
    __shared__ float s_w8[OC][8];
    // prep conv weights, lane-duplicated (tiny, read once per tap not per oc)
    __shared__ u64 s_pwd[KS * 3], s_pbd[KS], s_mwd[KS * 3], s_mbd[KS];

    const int tid = threadIdx.x;
    for (int i = tid; i < OC * 8; i += blockDim.x) {
        const int oc = i >> 3, k = i & 7;
        s_w8[oc][k] = (k < KS) ? cw[oc * KS + k] : cb[oc];
    }
    if (tid < KS * 3) {
        const float a = pw[tid], c = mw[tid];
        s_pwd[tid] = pack2(a, a);
        s_mwd[tid] = pack2(c, c);
    }
    if (tid < KS) {
        const float a = pb[tid], c = mb[tid];
        s_pbd[tid] = pack2(a, a);
        s_mbd[tid] = pack2(c, c);
    }
    __syncthreads();

    const int t  = blockIdx.x * blockDim.x + tid;   // 2^19 threads total
    const int c2 = t & 7;                           // channel pair (2 floats)
    const int l  = (t >> 3) & (LL - 1);
    const int b  = t >> 15;                         // 8*LL = 2^15 per batch

    const float* xb = x + b * (LL * CC);
    const float2* xb2 = (const float2*)xb;

    // 3-tap window over 2 channels (zero padding at the edges, pad=1 conv)
    float2 sm1 = (l > 0)      ? __ldg(&xb2[(l - 1) * 8 + c2]) : make_float2(0.f, 0.f);
    float2 s0  =                __ldg(&xb2[l * 8 + c2]);
    float2 sp1 = (l < LL - 1) ? __ldg(&xb2[(l + 1) * 8 + c2]) : make_float2(0.f, 0.f);

    // channel-paired window values for f32x2 prep convs
    const u64 winp0 = pack2(sm1.x, sm1.y);
    const u64 winp1 = pack2(s0.x,  s0.y);
    const u64 winp2 = pack2(sp1.x, sp1.y);

    const float lf1 = (float)(l + 1);               // p_0 is 1-indexed

    float vk[2][KS];
    #pragma unroll
    for (int k = 0; k < KS; ++k) {
        // offset + mask convs, both channels at once
        u64 off2 = ffma2(winp2, s_pwd[k * 3 + 2],
                   ffma2(winp1, s_pwd[k * 3 + 1],
                   ffma2(winp0, s_pwd[k * 3 + 0], s_pbd[k])));
        u64 z2   = ffma2(winp2, s_mwd[k * 3 + 2],
                   ffma2(winp1, s_mwd[k * 3 + 1],
                   ffma2(winp0, s_mwd[k * 3 + 0], s_mbd[k])));
        float offc[2], zc[2];
        unpack2(off2, offc[0], offc[1]);
        unpack2(z2,   zc[0],   zc[1]);

        const float pbase = lf1 + (float)(k - 3);   // single FADD, const folded
        #pragma unroll
        for (int i = 0; i < 2; ++i) {
            float m   = __fdividef(1.f, 1.f + __expf(-zc[i]));  // sigmoid
            float p   = pbase + offc[i];
            float qlt = fminf(fmaxf(floorf(p), 0.f), (float)(LL - 1));
            float qrb = fminf(qlt + 1.f, (float)(LL - 1));
            float pc  = fminf(fmaxf(p, 0.f), (float)(LL - 1));
            float glt = 1.f + (qlt - pc);
            float grb = 1.f - (qrb - pc);
            const int ch = c2 * 2 + i;
            float xlt = xb[(int)qlt * CC + ch];
            float xrb = xb[(int)qrb * CC + ch];
            vk[i][k] = (glt * xlt + grb * xrb) * m;
        }
    }

    // tap-paired packed v values (natural pairs, no duplication)
    u64 v01[2], v23[2], v45[2], v6b[2];
    #pragma unroll
    for (int i = 0; i < 2; ++i) {
        v01[i] = pack2(vk[i][0], vk[i][1]);
        v23[i] = pack2(vk[i][2], vk[i][3]);
        v45[i] = pack2(vk[i][4], vk[i][5]);
        v6b[i] = pack2(vk[i][6], 1.f);          // lane1 multiplies the bias
    }

    float2* out2 = (float2*)out;
    const int obase = ((b * OC) * LL + l) * 8 + c2;     // float2 index

    #pragma unroll 8
    for (int oc = 0; oc < OC; ++oc) {
        const ulonglong2* row = (const ulonglong2*)s_w8[oc];
        ulonglong2 wa = row[0];     // (w0,w1) (w2,w3)
        ulonglong2 wb = row[1];     // (w4,w5) (w6,bias)
        float r[2];
        #pragma unroll
        for (int i = 0; i < 2; ++i) {
            u64 acc = fmul2(v6b[i], wb.y);              // (w6*v6, bias)
            acc = ffma2(v01[i], wa.x, acc);
            acc = ffma2(v23[i], wa.y, acc);
            acc = ffma2(v45[i], wb.x, acc);
            float lo, hi;
            unpack2(acc, lo, hi);
            r[i] = lo + hi;
        }
        __stcs(&out2[obase + oc * (LL * 8)], make_float2(r[0], r[1]));
    }
}

extern "C" void kernel_launch(void* const* d_in, const int* in_sizes, int n_in,
                              void* d_out, int out_size)
{
    const float* x  = (const float*)d_in[0];
    const float* pw = (const float*)d_in[1];
    const float* pb = (const float*)d_in[2];
    const float* mw = (const float*)d_in[3];
    const float* mb = (const float*)d_in[4];
    const float* cw = (const float*)d_in[5];
    const float* cb = (const float*)d_in[6];
    float* out = (float*)d_out;

    // 16 batches * 4096 positions * 8 channel-pairs = 524288 threads
    deform_conv_kernel<<<2048, 256>>>(x, pw, pb, mw, mb, cw, cb, out);
}